// round 3
// baseline (speedup 1.0000x reference)
#include <cuda_runtime.h>

#define T_ 8
#define B_ 4
#define C_ 128
#define HW_ 9216      // 96*96
#define HW4_ 2304     // HW_/4
#define NMAP 36       // T*B + B maps to resize
#define NTB 32        // T*B

// scratch (static __device__ — no allocation)
__device__ float g_tv[B_ * HW_];
__device__ float g_rv[NTB * HW_];
__device__ float g_cm[NTB * HW_];
__device__ float g_pgs[NTB * 72];   // 9 pixel tiles x 8 c-chunks
__device__ float g_pvs[NTB * 9];    // 9 pixel tiles

// ---------------------------------------------------------------------------
// 1) antialiased (jax-style) 384->96 resize + threshold > 0.5
// ---------------------------------------------------------------------------
__global__ void resize_kernel(const float* __restrict__ tvmap,
                              const float* __restrict__ rvmaps) {
    int idx = blockIdx.x * blockDim.x + threadIdx.x;
    if (idx >= NMAP * HW_) return;
    int m = idx / HW_;
    int p = idx - m * HW_;
    int oy = p / 96, ox = p - oy * 96;

    const float* src = (m < B_) ? (tvmap + (size_t)m * 147456)
                                : (rvmaps + (size_t)(m - B_) * 147456);

    const float wtab[8] = {1.f, 3.f, 5.f, 7.f, 7.f, 5.f, 3.f, 1.f};
    int iy0 = 4 * oy - 2, ix0 = 4 * ox - 2;

    float wx[8];
    float wxs = 0.f;
#pragma unroll
    for (int k = 0; k < 8; k++) {
        int ix = ix0 + k;
        wx[k] = (ix >= 0 && ix < 384) ? wtab[k] : 0.f;
        wxs += wx[k];
    }

    float acc = 0.f, wys = 0.f;
#pragma unroll
    for (int ky = 0; ky < 8; ky++) {
        int iy = iy0 + ky;
        if (iy < 0 || iy >= 384) continue;
        wys += wtab[ky];
        const float* row = src + iy * 384;
        float ra = 0.f;
#pragma unroll
        for (int kx = 0; kx < 8; kx++) {
            if (wx[kx] != 0.f) ra += wx[kx] * row[ix0 + kx];
        }
        acc += wtab[ky] * ra;
    }
    float val = acc / (wys * wxs);
    float bin = (val > 0.5f) ? 1.f : 0.f;
    if (m < B_) g_tv[m * HW_ + p] = bin;
    else        g_rv[(m - B_) * HW_ + p] = bin;
}

// ---------------------------------------------------------------------------
// 2) masked correlation partials, ALL t accumulated per block (t_feat read 1x)
//    + t_feat passthrough to output. grid = (9 px tiles, 8 c-chunks of 16, 4 b)
// ---------------------------------------------------------------------------
__global__ void __launch_bounds__(256) pass1_kernel(const float* __restrict__ values,
                                                    float* __restrict__ d_out) {
    int b = blockIdx.z;
    int chunk = blockIdx.y;
    int c0 = chunk * 16;
    int i4 = blockIdx.x * 256 + threadIdx.x;   // 0..2303

    const float4* tf = (const float4*)values + ((size_t)b * C_ + c0) * HW4_ + i4;
    const float4* rf = (const float4*)values + ((size_t)(B_ + b) * C_ + c0) * HW4_ + i4;
    float4* outp = (float4*)d_out + ((size_t)b * 257 + c0) * HW4_ + i4;
    const size_t tstride = (size_t)B_ * C_ * HW4_;

    float4 acc[T_];
#pragma unroll
    for (int t = 0; t < T_; t++) acc[t] = make_float4(0.f, 0.f, 0.f, 0.f);

#pragma unroll 2
    for (int c = 0; c < 16; c++) {
        float4 a = __ldg(tf + c * HW4_);
        outp[c * HW4_] = a;   // t_feat -> out ch 0..127 (each element exactly once)
#pragma unroll
        for (int t = 0; t < T_; t++) {
            float4 r = __ldcs(rf + t * tstride + c * HW4_);
            acc[t].x += a.x * r.x; acc[t].y += a.y * r.y;
            acc[t].z += a.z * r.z; acc[t].w += a.w * r.w;
        }
    }

    float4 tv = ((const float4*)g_tv)[b * HW4_ + i4];
    float lg[T_], lv[T_];
#pragma unroll
    for (int t = 0; t < T_; t++) {
        float4 rv = ((const float4*)g_rv)[(t * B_ + b) * HW4_ + i4];
        float m0 = tv.x * rv.x, m1 = tv.y * rv.y, m2 = tv.z * rv.z, m3 = tv.w * rv.w;
        lg[t] = acc[t].x * m0 + acc[t].y * m1 + acc[t].z * m2 + acc[t].w * m3;
        lv[t] = m0 + m1 + m2 + m3;
    }

#pragma unroll
    for (int o = 16; o > 0; o >>= 1) {
#pragma unroll
        for (int t = 0; t < T_; t++)
            lg[t] += __shfl_down_sync(0xffffffffu, lg[t], o);
    }
    if (chunk == 0) {
#pragma unroll
        for (int o = 16; o > 0; o >>= 1) {
#pragma unroll
            for (int t = 0; t < T_; t++)
                lv[t] += __shfl_down_sync(0xffffffffu, lv[t], o);
        }
    }

    __shared__ float sg[8][T_], sv[8][T_];
    int lane = threadIdx.x & 31, w = threadIdx.x >> 5;
    if (lane == 0) {
#pragma unroll
        for (int t = 0; t < T_; t++) { sg[w][t] = lg[t]; sv[w][t] = lv[t]; }
    }
    __syncthreads();
    if (threadIdx.x < T_) {
        int t = threadIdx.x;
        float a = 0.f, v = 0.f;
#pragma unroll
        for (int i = 0; i < 8; i++) { a += sg[i][t]; v += sv[i][t]; }
        g_pgs[(t * B_ + b) * 72 + blockIdx.x * 8 + chunk] = a;
        if (chunk == 0) g_pvs[(t * B_ + b) * 9 + blockIdx.x] = v;
    }
}

// ---------------------------------------------------------------------------
// 3) fused gs-finalize + per-pixel softmax over T (scalar, 288 x 128)
// ---------------------------------------------------------------------------
__global__ void __launch_bounds__(128) cmatch_kernel(float* __restrict__ d_out) {
    const int BPB = HW_ / 128;           // 72 pixel-blocks per b
    int b = blockIdx.x / BPB;
    int pblk = blockIdx.x - b * BPB;
    int p = pblk * 128 + threadIdx.x;

    __shared__ float sgs[T_];
    if (threadIdx.x < T_) {
        int t = threadIdx.x;
        int tb = t * B_ + b;
        float gsum = 0.f, vsum = 0.f;
#pragma unroll
        for (int i = 0; i < 72; i++) gsum += g_pgs[tb * 72 + i];
#pragma unroll
        for (int i = 0; i < 9; i++) vsum += g_pvs[tb * 9 + i];
        float g = (vsum < 1e-4f) ? 0.f : (gsum / vsum) * (1.f / 128.f);
        sgs[t] = g;
        if (pblk == 0)
            d_out[(size_t)B_ * 257 * HW_ + (size_t)B_ * HW_ + tb] = g;
    }
    __syncthreads();

    float rvv[T_];
#pragma unroll
    for (int t = 0; t < T_; t++)
        rvv[t] = g_rv[(t * B_ + b) * HW_ + p];

    float mx = -1e30f;
#pragma unroll
    for (int t = 0; t < T_; t++) mx = fmaxf(mx, sgs[t] * rvv[t]);
    float cm[T_];
    float ms = 0.f;
#pragma unroll
    for (int t = 0; t < T_; t++) {
        float e = expf(sgs[t] * rvv[t] - mx) * rvv[t];
        cm[t] = e;
        ms += e;
    }
    float msd = ms + ((ms < 1e-4f) ? 1.f : 0.f);
    float inv = 1.f / msd;
#pragma unroll
    for (int t = 0; t < T_; t++)
        g_cm[(t * B_ + b) * HW_ + p] = cm[t] * inv;

    float cmask = 1.f - ms * inv;
    d_out[((size_t)b * 257 + 256) * HW_ + p] = cmask;                 // out ch 256
    d_out[(size_t)B_ * 257 * HW_ + (size_t)b * HW_ + p] = cmask;      // c_mask output
}

// ---------------------------------------------------------------------------
// 4) c_out[b,c,p] = sum_t r_feats * c_match.  grid = (9, 32 c-chunks of 4, 4 b)
// ---------------------------------------------------------------------------
__global__ void __launch_bounds__(256) pass2_kernel(const float* __restrict__ values,
                                                    float* __restrict__ d_out) {
    int i4 = blockIdx.x * 256 + threadIdx.x;   // 0..2303
    int c0 = blockIdx.y * 4;
    int b = blockIdx.z;

    float4 cm[T_];
#pragma unroll
    for (int t = 0; t < T_; t++)
        cm[t] = ((const float4*)g_cm)[(t * B_ + b) * HW4_ + i4];

    const float4* rfb = (const float4*)values;
    float4* outp = (float4*)d_out;
#pragma unroll
    for (int cc = 0; cc < 4; cc++) {
        int c = c0 + cc;
        float4 acc = make_float4(0.f, 0.f, 0.f, 0.f);
#pragma unroll
        for (int t = 0; t < T_; t++) {
            float4 r = __ldcs(rfb + ((size_t)(B_ + t * B_ + b) * C_ + c) * HW4_ + i4);
            acc.x += r.x * cm[t].x; acc.y += r.y * cm[t].y;
            acc.z += r.z * cm[t].z; acc.w += r.w * cm[t].w;
        }
        outp[((size_t)b * 257 + 128 + c) * HW4_ + i4] = acc;
    }
}

// ---------------------------------------------------------------------------
extern "C" void kernel_launch(void* const* d_in, const int* in_sizes, int n_in,
                              void* d_out, int out_size) {
    const float* values = (const float*)d_in[0];   // (9,4,128,96,96)
    const float* tvmap  = (const float*)d_in[1];   // (4,1,384,384)
    const float* rvmaps = (const float*)d_in[2];   // (8,4,1,384,384)
    float* out = (float*)d_out;

    resize_kernel<<<(NMAP * HW_ + 255) / 256, 256>>>(tvmap, rvmaps);

    dim3 g1(9, 8, B_);
    pass1_kernel<<<g1, 256>>>(values, out);

    cmatch_kernel<<<B_ * (HW_ / 128), 128>>>(out);

    dim3 g2(9, 32, B_);
    pass2_kernel<<<g2, 256>>>(values, out);
}

// round 4
// speedup vs baseline: 1.0695x; 1.0695x over previous
#include <cuda_runtime.h>

#define T_ 8
#define B_ 4
#define C_ 128
#define HW_ 9216      // 96*96
#define HW4_ 2304     // HW_/4
#define NMAP 36       // T*B + B maps to resize
#define NTB 32        // T*B
#define NP1 288       // pass1 partials per tb: 18 px-tiles * 16 c-chunks
#define NPV 18        // vsum partials per tb

// scratch (static __device__ — no allocation)
__device__ float g_tv[B_ * HW_];
__device__ float g_rv[NTB * HW_];
__device__ float g_cm[NTB * HW_];
__device__ float g_pgs[NTB * NP1];
__device__ float g_pvs[NTB * NPV];
__device__ float g_gs[NTB];

// ---------------------------------------------------------------------------
// 1) antialiased (jax-style) 384->96 resize + threshold > 0.5
// ---------------------------------------------------------------------------
__global__ void resize_kernel(const float* __restrict__ tvmap,
                              const float* __restrict__ rvmaps) {
    int idx = blockIdx.x * blockDim.x + threadIdx.x;
    if (idx >= NMAP * HW_) return;
    int m = idx / HW_;
    int p = idx - m * HW_;
    int oy = p / 96, ox = p - oy * 96;

    const float* src = (m < B_) ? (tvmap + (size_t)m * 147456)
                                : (rvmaps + (size_t)(m - B_) * 147456);

    const float wtab[8] = {1.f, 3.f, 5.f, 7.f, 7.f, 5.f, 3.f, 1.f};
    int iy0 = 4 * oy - 2, ix0 = 4 * ox - 2;

    float wx[8];
    float wxs = 0.f;
#pragma unroll
    for (int k = 0; k < 8; k++) {
        int ix = ix0 + k;
        wx[k] = (ix >= 0 && ix < 384) ? wtab[k] : 0.f;
        wxs += wx[k];
    }

    float acc = 0.f, wys = 0.f;
#pragma unroll
    for (int ky = 0; ky < 8; ky++) {
        int iy = iy0 + ky;
        if (iy < 0 || iy >= 384) continue;
        wys += wtab[ky];
        const float* row = src + iy * 384;
        float ra = 0.f;
#pragma unroll
        for (int kx = 0; kx < 8; kx++) {
            if (wx[kx] != 0.f) ra += wx[kx] * row[ix0 + kx];
        }
        acc += wtab[ky] * ra;
    }
    float val = acc / (wys * wxs);
    float bin = (val > 0.5f) ? 1.f : 0.f;
    if (m < B_) g_tv[m * HW_ + p] = bin;
    else        g_rv[(m - B_) * HW_ + p] = bin;
}

// ---------------------------------------------------------------------------
// 2) masked correlation partials, ALL t accumulated per block (t_feat read 1x)
//    + t_feat passthrough. grid = (18 px-tiles, 16 c-chunks of 8, 4 b), 128 thr
// ---------------------------------------------------------------------------
__global__ void __launch_bounds__(128) pass1_kernel(const float* __restrict__ values,
                                                    float* __restrict__ d_out) {
    int b = blockIdx.z;
    int chunk = blockIdx.y;
    int c0 = chunk * 8;
    int i4 = blockIdx.x * 128 + threadIdx.x;   // 0..2303

    const float4* tf = (const float4*)values + ((size_t)b * C_ + c0) * HW4_ + i4;
    const float4* rf = (const float4*)values + ((size_t)(B_ + b) * C_ + c0) * HW4_ + i4;
    float4* outp = (float4*)d_out + ((size_t)b * 257 + c0) * HW4_ + i4;
    const size_t tstride = (size_t)B_ * C_ * HW4_;

    float4 acc[T_];
#pragma unroll
    for (int t = 0; t < T_; t++) acc[t] = make_float4(0.f, 0.f, 0.f, 0.f);

#pragma unroll
    for (int c = 0; c < 8; c++) {
        float4 a = __ldg(tf + c * HW4_);
        outp[c * HW4_] = a;   // t_feat -> out ch 0..127 (each element exactly once)
#pragma unroll
        for (int t = 0; t < T_; t++) {
            float4 r = __ldcs(rf + t * tstride + c * HW4_);
            acc[t].x += a.x * r.x; acc[t].y += a.y * r.y;
            acc[t].z += a.z * r.z; acc[t].w += a.w * r.w;
        }
    }

    float4 tv = ((const float4*)g_tv)[b * HW4_ + i4];
    float lg[T_], lv[T_];
#pragma unroll
    for (int t = 0; t < T_; t++) {
        float4 rv = ((const float4*)g_rv)[(t * B_ + b) * HW4_ + i4];
        float m0 = tv.x * rv.x, m1 = tv.y * rv.y, m2 = tv.z * rv.z, m3 = tv.w * rv.w;
        lg[t] = acc[t].x * m0 + acc[t].y * m1 + acc[t].z * m2 + acc[t].w * m3;
        lv[t] = m0 + m1 + m2 + m3;
    }

#pragma unroll
    for (int o = 16; o > 0; o >>= 1) {
#pragma unroll
        for (int t = 0; t < T_; t++)
            lg[t] += __shfl_down_sync(0xffffffffu, lg[t], o);
    }
    if (chunk == 0) {
#pragma unroll
        for (int o = 16; o > 0; o >>= 1) {
#pragma unroll
            for (int t = 0; t < T_; t++)
                lv[t] += __shfl_down_sync(0xffffffffu, lv[t], o);
        }
    }

    __shared__ float sg[4][T_], sv[4][T_];
    int lane = threadIdx.x & 31, w = threadIdx.x >> 5;
    if (lane == 0) {
#pragma unroll
        for (int t = 0; t < T_; t++) { sg[w][t] = lg[t]; sv[w][t] = lv[t]; }
    }
    __syncthreads();
    if (threadIdx.x < T_) {
        int t = threadIdx.x;
        float a = 0.f, v = 0.f;
#pragma unroll
        for (int i = 0; i < 4; i++) { a += sg[i][t]; v += sv[i][t]; }
        g_pgs[(t * B_ + b) * NP1 + blockIdx.x * 16 + chunk] = a;
        if (chunk == 0) g_pvs[(t * B_ + b) * NPV + blockIdx.x] = v;
    }
}

// ---------------------------------------------------------------------------
// 3) finalize gs: 256 threads, 8 lanes per tb reduce 288 partials
// ---------------------------------------------------------------------------
__global__ void __launch_bounds__(256) finalize_kernel(float* __restrict__ d_out) {
    int tb = threadIdx.x >> 3;
    int j = threadIdx.x & 7;
    float gsum = 0.f;
#pragma unroll
    for (int k = 0; k < NP1 / 8; k++) gsum += g_pgs[tb * NP1 + j + 8 * k];
#pragma unroll
    for (int o = 4; o > 0; o >>= 1)
        gsum += __shfl_down_sync(0xffffffffu, gsum, o, 8);
    if (j == 0) {
        float vsum = 0.f;
#pragma unroll
        for (int i = 0; i < NPV; i++) vsum += g_pvs[tb * NPV + i];
        float g = (vsum < 1e-4f) ? 0.f : (gsum / vsum) * (1.f / 128.f);
        g_gs[tb] = g;
        d_out[(size_t)B_ * 257 * HW_ + (size_t)B_ * HW_ + tb] = g;
    }
}

// ---------------------------------------------------------------------------
// 4) per-pixel softmax over T (scalar, 288 x 128)
// ---------------------------------------------------------------------------
__global__ void __launch_bounds__(128) cmatch_kernel(float* __restrict__ d_out) {
    const int BPB = HW_ / 128;           // 72 pixel-blocks per b
    int b = blockIdx.x / BPB;
    int pblk = blockIdx.x - b * BPB;
    int p = pblk * 128 + threadIdx.x;

    __shared__ float sgs[T_];
    if (threadIdx.x < T_) sgs[threadIdx.x] = g_gs[threadIdx.x * B_ + b];
    __syncthreads();

    float rvv[T_];
#pragma unroll
    for (int t = 0; t < T_; t++)
        rvv[t] = g_rv[(t * B_ + b) * HW_ + p];

    float mx = -1e30f;
#pragma unroll
    for (int t = 0; t < T_; t++) mx = fmaxf(mx, sgs[t] * rvv[t]);
    float cm[T_];
    float ms = 0.f;
#pragma unroll
    for (int t = 0; t < T_; t++) {
        float e = expf(sgs[t] * rvv[t] - mx) * rvv[t];
        cm[t] = e;
        ms += e;
    }
    float msd = ms + ((ms < 1e-4f) ? 1.f : 0.f);
    float inv = 1.f / msd;
#pragma unroll
    for (int t = 0; t < T_; t++)
        g_cm[(t * B_ + b) * HW_ + p] = cm[t] * inv;

    float cmask = 1.f - ms * inv;
    d_out[((size_t)b * 257 + 256) * HW_ + p] = cmask;                 // out ch 256
    d_out[(size_t)B_ * 257 * HW_ + (size_t)b * HW_ + p] = cmask;      // c_mask output
}

// ---------------------------------------------------------------------------
// 5) c_out[b,c,p] = sum_t r_feats * c_match.  grid = (9, 32 c-chunks of 4, 4 b)
//    t outer, cm reloaded per t (L2-hot) -> fewer regs, higher occupancy
// ---------------------------------------------------------------------------
__global__ void __launch_bounds__(256) pass2_kernel(const float* __restrict__ values,
                                                    float* __restrict__ d_out) {
    int i4 = blockIdx.x * 256 + threadIdx.x;   // 0..2303
    int c0 = blockIdx.y * 4;
    int b = blockIdx.z;

    const float4* rfb = (const float4*)values + ((size_t)(B_ + b) * C_ + c0) * HW4_ + i4;
    const float4* cmp = (const float4*)g_cm + (size_t)b * HW4_ + i4;
    const size_t tstride = (size_t)B_ * C_ * HW4_;
    const size_t cmstride = (size_t)B_ * HW4_;

    float4 acc0 = make_float4(0.f, 0.f, 0.f, 0.f);
    float4 acc1 = acc0, acc2 = acc0, acc3 = acc0;
#pragma unroll
    for (int t = 0; t < T_; t++) {
        float4 cm = __ldg(cmp + t * cmstride);
        float4 r0 = __ldcs(rfb + t * tstride + 0 * HW4_);
        float4 r1 = __ldcs(rfb + t * tstride + 1 * HW4_);
        float4 r2 = __ldcs(rfb + t * tstride + 2 * HW4_);
        float4 r3 = __ldcs(rfb + t * tstride + 3 * HW4_);
        acc0.x += r0.x * cm.x; acc0.y += r0.y * cm.y; acc0.z += r0.z * cm.z; acc0.w += r0.w * cm.w;
        acc1.x += r1.x * cm.x; acc1.y += r1.y * cm.y; acc1.z += r1.z * cm.z; acc1.w += r1.w * cm.w;
        acc2.x += r2.x * cm.x; acc2.y += r2.y * cm.y; acc2.z += r2.z * cm.z; acc2.w += r2.w * cm.w;
        acc3.x += r3.x * cm.x; acc3.y += r3.y * cm.y; acc3.z += r3.z * cm.z; acc3.w += r3.w * cm.w;
    }

    float4* outp = (float4*)d_out + ((size_t)b * 257 + 128 + c0) * HW4_ + i4;
    outp[0 * HW4_] = acc0;
    outp[1 * HW4_] = acc1;
    outp[2 * HW4_] = acc2;
    outp[3 * HW4_] = acc3;
}

// ---------------------------------------------------------------------------
extern "C" void kernel_launch(void* const* d_in, const int* in_sizes, int n_in,
                              void* d_out, int out_size) {
    const float* values = (const float*)d_in[0];   // (9,4,128,96,96)
    const float* tvmap  = (const float*)d_in[1];   // (4,1,384,384)
    const float* rvmaps = (const float*)d_in[2];   // (8,4,1,384,384)
    float* out = (float*)d_out;

    resize_kernel<<<(NMAP * HW_ + 255) / 256, 256>>>(tvmap, rvmaps);

    dim3 g1(18, 16, B_);
    pass1_kernel<<<g1, 128>>>(values, out);

    finalize_kernel<<<1, 256>>>(out);

    cmatch_kernel<<<B_ * (HW_ / 128), 128>>>(out);

    dim3 g2(9, 32, B_);
    pass2_kernel<<<g2, 256>>>(values, out);
}